// round 10
// baseline (speedup 1.0000x reference)
#include <cuda_runtime.h>
#include <cstdint>

#define CC 96
#define HH 256
#define WW 256
#define KK 7
#define SS 16   // SMEM ring slots (rows) per y-half

__device__ __forceinline__ void fma2(unsigned long long &d,
                                     unsigned long long a,
                                     unsigned long long b) {
    asm("fma.rn.f32x2 %0, %1, %2, %0;" : "+l"(d) : "l"(a), "l"(b));
}
__device__ __forceinline__ unsigned long long pk2(float lo, float hi) {
    return (unsigned long long)__float_as_uint(lo) |
           ((unsigned long long)__float_as_uint(hi) << 32);
}
__device__ __forceinline__ void upk2(unsigned long long v, float &lo, float &hi) {
    lo = __uint_as_float((unsigned int)(v & 0xffffffffull));
    hi = __uint_as_float((unsigned int)(v >> 32));
}
__device__ __forceinline__ void cpasync16(unsigned dst, const float* src) {
    asm volatile("cp.async.ca.shared.global [%0], [%1], 16;" :: "r"(dst), "l"(src));
}
#define CP_COMMIT() asm volatile("cp.async.commit_group;" ::: "memory")
#define CP_WAIT4()  asm volatile("cp.async.wait_group 4;"  ::: "memory")

// blockDim=(64,2), grid=(1,2,nimg). Thread: 4 cols (float4), 64-row strip.
// Fast path (r < 5/3): folded 11-tap integer-offset conv (span -5..+5).
//   Feed: cp.async streams row y+11 (own 16B) into a 16-slot SMEM ring;
//         wait_group 4 keeps ~4 rows (2KB/warp) in flight — MLP without regs.
//         Prologue stages EXACTLY 16 rows (y0-5..y0+10): bijective with slots.
//   H conv: 12-slot REGISTER ring (static slots), filled from SMEM via LDS.
//   W conv: 14-col window (x4-5..x4+8), narrow side LDGs (L1 hits via .ca).
__global__ __launch_bounds__(128, 6) void caxial_kernel(const float* __restrict__ x,
                                                        const float* __restrict__ wh,
                                                        const float* __restrict__ ww,
                                                        const float* __restrict__ rp,
                                                        float* __restrict__ out) {
    __shared__ ulonglong2 smem_ring[2][SS][64];

    const int c  = blockIdx.z % CC;
    const int tx = threadIdx.x;                               // 0..63
    const int ty = threadIdx.y;                               // 0..1
    const int strip = blockIdx.y * 2 + ty;                    // 0..3
    const int x4 = tx * 4;
    const int y0 = strip * 64;
    const float* xc = x   + (size_t)blockIdx.z * (HH * WW);
    float*       oc = out + (size_t)blockIdx.z * (HH * WW);

    float rv = rp[0];
    if (rv < 1.0f) rv = 1.0f;

    float whv[KK], wwv[KK], fri[KK];
    int   k0i[KK];
    #pragma unroll
    for (int i = 0; i < KK; i++) {
        float ofr = (float)(i - 3) * rv;
        float fl  = floorf(ofr);
        k0i[i] = (int)fl + 5;                 // tap index base: dr = k - 5
        fri[i] = ofr - fl;
        whv[i] = wh[c * KK + i];
        wwv[i] = ww[c * KK + i];
    }
    // fast: all folded taps fall in k = 0..10  (r < 5/3)
    const bool fast = (k0i[0] >= 0) && (k0i[KK - 1] + 1 <= 10);

    if (fast) {
        // Fold 7 bilinear taps into 11 integer-offset weights (dc/dr = k - 5)
        unsigned long long cwh2[11];
        float cww[11];
        #pragma unroll
        for (int k = 0; k < 11; k++) {
            float sh = 0.f, sw = 0.f;
            #pragma unroll
            for (int i = 0; i < KK; i++) {
                if (k0i[i] == k)     { sh += whv[i] * (1.f - fri[i]); sw += wwv[i] * (1.f - fri[i]); }
                if (k0i[i] + 1 == k) { sh += whv[i] * fri[i];         sw += wwv[i] * fri[i]; }
            }
            cwh2[k] = pk2(sh, sh);
            cww[k]  = sw;
        }

        // SMEM staging prologue: rows y0-5 .. y0+10 (EXACTLY 16 rows -> 16 slots,
        // no collision). One commit-group per row. slot(row) = row & 15.
        #pragma unroll
        for (int t = -5; t <= 10; t++) {
            int row = y0 + t;
            if (row >= 0)   // row < HH always true in prologue (y0 <= 192, t <= 10)
                cpasync16((unsigned)__cvta_generic_to_shared(&smem_ring[ty][row & 15][tx]),
                          xc + (size_t)row * WW + x4);
            CP_COMMIT();
        }
        CP_WAIT4();   // 16 groups committed, <=4 pending -> rows y0-5..y0+6 ready

        // Register ring: 12 slots; slot(row) = (row - y0 + 5) % 12. Fill from SMEM.
        ulonglong2 ring[12];
        #pragma unroll
        for (int t = -5; t <= 6; t++) {
            int row = y0 + t;
            ring[t + 5] = (row >= 0) ? smem_ring[ty][row & 15][tx]
                                     : make_ulonglong2(0ull, 0ull);
        }

        // Side-load predicates: window cols x4-5 .. x4+8
        const bool eSL = (x4 >= 8);           // col  x4-5         (LDG.32)
        const bool eL1 = (x4 >= 4);           // cols x4-4..x4-1   (LDG.128)
        const bool eR1 = (tx <= 62);          // cols x4+4..x4+7   (LDG.128)
        const bool eSR = (tx <= 61);          // col  x4+8         (LDG.32)
        const float4 z4 = make_float4(0.f, 0.f, 0.f, 0.f);

        // Body for row y with register-ring phase u (compile-time constant).
        #define CAX_BODY(yy, uu)                                                          \
        {                                                                                 \
            const int y = (yy);                                                           \
            /* Stream row y+11 into SMEM (own 16B); one group per row.        */          \
            /* Overwrites slot of row y-5 (last read 11 iterations ago).      */          \
            {                                                                             \
                int wrow = y + 11;                                                        \
                if (wrow < HH)                                                            \
                    cpasync16((unsigned)__cvta_generic_to_shared(                         \
                                  &smem_ring[ty][wrow & 15][tx]),                         \
                              xc + (size_t)wrow * WW + x4);                               \
                CP_COMMIT();                                                              \
                CP_WAIT4();      /* completed through row y+7; we read y+6 */             \
            }                                                                             \
            /* Register-ring fill: row y+6 from SMEM (LDS.128) */                         \
            {                                                                             \
                int row = y + 6;                                                          \
                ulonglong2 v = make_ulonglong2(0ull, 0ull);                               \
                if (row < HH) v = smem_ring[ty][row & 15][tx];                            \
                ring[((uu) + 11) % 12] = v;                                               \
            }                                                                             \
            /* Side loads for row y (L1 hits; lines brought by cp.async.ca) */            \
            const float* rowp = xc + (size_t)y * WW;                                      \
            float  sl = eSL ? rowp[x4 - 5] : 0.f;                                         \
            float4 l1 = eL1 ? *reinterpret_cast<const float4*>(rowp + x4 - 4) : z4;       \
            float4 r1 = eR1 ? *reinterpret_cast<const float4*>(rowp + x4 + 4) : z4;       \
            float  sr = eSR ? rowp[x4 + 8] : 0.f;                                         \
                                                                                          \
            ulonglong2 ctr = ring[((uu) + 5) % 12];     /* row y */                       \
            float c0, c1, c2, c3;                                                         \
            upk2(ctr.x, c0, c1);                                                          \
            upk2(ctr.y, c2, c3);                                                          \
                                                                                          \
            unsigned long long acc01 = ctr.x;                                             \
            unsigned long long acc23 = ctr.y;                                             \
            _Pragma("unroll")                                                             \
            for (int k = 0; k < 11; k++) {              /* row y + (k-5) */               \
                ulonglong2 rv2 = ring[((uu) + k) % 12];                                   \
                fma2(acc01, cwh2[k], rv2.x);                                              \
                fma2(acc23, cwh2[k], rv2.y);                                              \
            }                                                                             \
            float a0, a1, a2, a3;                                                         \
            upk2(acc01, a0, a1);                                                          \
            upk2(acc23, a2, a3);                                                          \
                                                                                          \
            float win[14];                                                                \
            win[0]  = sl;                                                                 \
            win[1]  = l1.x; win[2]  = l1.y; win[3]  = l1.z; win[4]  = l1.w;               \
            win[5]  = c0;   win[6]  = c1;   win[7]  = c2;   win[8]  = c3;                 \
            win[9]  = r1.x; win[10] = r1.y; win[11] = r1.z; win[12] = r1.w;               \
            win[13] = sr;                                                                 \
            _Pragma("unroll")                                                             \
            for (int k = 0; k < 11; k++) {              /* col (x4+j)+(k-5) */            \
                float w = cww[k];                                                         \
                a0 += w * win[k];                                                         \
                a1 += w * win[k + 1];                                                     \
                a2 += w * win[k + 2];                                                     \
                a3 += w * win[k + 3];                                                     \
            }                                                                             \
            __stcs(reinterpret_cast<float4*>(oc + (size_t)y * WW + x4),                   \
                   make_float4(a0, a1, a2, a3));                                          \
        }

        #pragma unroll 1
        for (int g = 0; g < 5; g++) {                 // 5 groups of 12 rows
            int ybase = y0 + g * 12;
            #pragma unroll
            for (int u = 0; u < 12; u++) {
                CAX_BODY(ybase + u, u)
            }
        }
        {                                             // tail: 4 rows (60..63)
            int ybase = y0 + 60;                      // 60 % 12 == 0 -> same phases
            #pragma unroll
            for (int u = 0; u < 4; u++) {
                CAX_BODY(ybase + u, u)
            }
        }
        #undef CAX_BODY
    } else {
        // Generic path: direct 7-tap bilinear gather along both axes.
        #pragma unroll 1
        for (int yy = 0; yy < 64; yy++) {
            int y = y0 + yy;
            float acc[4];
            #pragma unroll
            for (int j = 0; j < 4; j++) acc[j] = xc[(size_t)y * WW + x4 + j];
            #pragma unroll
            for (int i = 0; i < KK; i++) {
                int   d  = k0i[i] - 5;
                float fr = fri[i];
                int r0 = y + d, r1 = r0 + 1;
                #pragma unroll
                for (int j = 0; j < 4; j++) {
                    int col = x4 + j;
                    float s0 = (r0 >= 0 && r0 < HH) ? xc[(size_t)r0 * WW + col] : 0.f;
                    float s1 = (r1 >= 0 && r1 < HH) ? xc[(size_t)r1 * WW + col] : 0.f;
                    acc[j] += whv[i] * (s0 * (1.f - fr) + s1 * fr);
                    int c0i = col + d, c1i = c0i + 1;
                    float t0 = (c0i >= 0 && c0i < WW) ? xc[(size_t)y * WW + c0i] : 0.f;
                    float t1 = (c1i >= 0 && c1i < WW) ? xc[(size_t)y * WW + c1i] : 0.f;
                    acc[j] += wwv[i] * (t0 * (1.f - fr) + t1 * fr);
                }
            }
            #pragma unroll
            for (int j = 0; j < 4; j++) oc[(size_t)y * WW + x4 + j] = acc[j];
        }
    }
}

extern "C" void kernel_launch(void* const* d_in, const int* in_sizes, int n_in,
                              void* d_out, int out_size) {
    const float* x  = (const float*)d_in[0];
    const float* wh = (const float*)d_in[1];
    const float* ww = (const float*)d_in[2];
    const float* r  = (const float*)d_in[3];
    float* out = (float*)d_out;

    int nimg = in_sizes[0] / (HH * WW);   // B*C = 768

    dim3 blk(64, 2, 1);
    dim3 grd(1, 2, nimg);
    caxial_kernel<<<grd, blk>>>(x, wh, ww, r, out);
}

// round 11
// speedup vs baseline: 1.0843x; 1.0843x over previous
#include <cuda_runtime.h>
#include <cstdint>

#define CC 96
#define HH 256
#define WW 256
#define KK 7
#define SS 16   // SMEM ring slots (rows) per y-half

__device__ __forceinline__ void fma2(unsigned long long &d,
                                     unsigned long long a,
                                     unsigned long long b) {
    asm("fma.rn.f32x2 %0, %1, %2, %0;" : "+l"(d) : "l"(a), "l"(b));
}
__device__ __forceinline__ unsigned long long pk2(float lo, float hi) {
    return (unsigned long long)__float_as_uint(lo) |
           ((unsigned long long)__float_as_uint(hi) << 32);
}
__device__ __forceinline__ void upk2(unsigned long long v, float &lo, float &hi) {
    lo = __uint_as_float((unsigned int)(v & 0xffffffffull));
    hi = __uint_as_float((unsigned int)(v >> 32));
}
__device__ __forceinline__ void cpasync16(unsigned dst, const float* src) {
    asm volatile("cp.async.ca.shared.global [%0], [%1], 16;" :: "r"(dst), "l"(src));
}
#define CP_COMMIT() asm volatile("cp.async.commit_group;" ::: "memory")
#define CP_WAIT0()  asm volatile("cp.async.wait_group 0;"  ::: "memory")
#define CP_WAIT1()  asm volatile("cp.async.wait_group 1;"  ::: "memory")

// blockDim=(64,2), grid=(1,2,nimg). Thread: 4 cols (float4), 64-row strip.
// Fast path (r < 5/3): folded 11-tap integer-offset conv (span -5..+5).
//   Feed: cp.async in 4-ROW GROUPS (stage rows Y+10..Y+13 at window top,
//         one commit + wait_group 1 per 4 iterations). The wait at window Y
//         targets the group issued at window Y-4 (~4 full iterations of slack).
//         Each thread stages only its own 16B -> no barriers needed.
//   H conv: 12-slot REGISTER ring (static slots), filled from SMEM via LDS.
//   W conv: 14-col window (x4-5..x4+8), narrow side LDGs (L1 hits via .ca).
__global__ __launch_bounds__(128, 6) void caxial_kernel(const float* __restrict__ x,
                                                        const float* __restrict__ wh,
                                                        const float* __restrict__ ww,
                                                        const float* __restrict__ rp,
                                                        float* __restrict__ out) {
    __shared__ ulonglong2 smem_ring[2][SS][64];

    const int c  = blockIdx.z % CC;
    const int tx = threadIdx.x;                               // 0..63
    const int ty = threadIdx.y;                               // 0..1
    const int strip = blockIdx.y * 2 + ty;                    // 0..3
    const int x4 = tx * 4;
    const int y0 = strip * 64;
    const int yEnd = y0 + 69;                                 // last row any fill reads
    const float* xc = x   + (size_t)blockIdx.z * (HH * WW);
    float*       oc = out + (size_t)blockIdx.z * (HH * WW);

    float rv = rp[0];
    if (rv < 1.0f) rv = 1.0f;

    float whv[KK], wwv[KK], fri[KK];
    int   k0i[KK];
    #pragma unroll
    for (int i = 0; i < KK; i++) {
        float ofr = (float)(i - 3) * rv;
        float fl  = floorf(ofr);
        k0i[i] = (int)fl + 5;                 // tap index base: dr = k - 5
        fri[i] = ofr - fl;
        whv[i] = wh[c * KK + i];
        wwv[i] = ww[c * KK + i];
    }
    // fast: all folded taps fall in k = 0..10  (r < 5/3)
    const bool fast = (k0i[0] >= 0) && (k0i[KK - 1] + 1 <= 10);

    if (fast) {
        // Fold 7 bilinear taps into 11 integer-offset weights (dc/dr = k - 5)
        unsigned long long cwh2[11];
        float cww[11];
        #pragma unroll
        for (int k = 0; k < 11; k++) {
            float sh = 0.f, sw = 0.f;
            #pragma unroll
            for (int i = 0; i < KK; i++) {
                if (k0i[i] == k)     { sh += whv[i] * (1.f - fri[i]); sw += wwv[i] * (1.f - fri[i]); }
                if (k0i[i] + 1 == k) { sh += whv[i] * fri[i];         sw += wwv[i] * fri[i]; }
            }
            cwh2[k] = pk2(sh, sh);
            cww[k]  = sw;
        }

        // SMEM staging prologue: rows y0-5 .. y0+9 (15 rows -> 16 slots, no
        // collision). 3 commit-groups of 5 rows. slot(row) = row & 15.
        #pragma unroll
        for (int t = -5; t <= 9; t++) {
            int row = y0 + t;
            if (row >= 0)   // row < HH always true in prologue (y0+9 <= 201)
                cpasync16((unsigned)__cvta_generic_to_shared(&smem_ring[ty][row & 15][tx]),
                          xc + (size_t)row * WW + x4);
            if (t == -1 || t == 4 || t == 9) CP_COMMIT();
        }
        CP_WAIT0();   // all 15 prologue rows staged

        // Register ring: 12 slots; slot(row) = (row - y0 + 5) % 12. Fill from SMEM.
        ulonglong2 ring[12];
        #pragma unroll
        for (int t = -5; t <= 6; t++) {
            int row = y0 + t;
            ring[t + 5] = (row >= 0) ? smem_ring[ty][row & 15][tx]
                                     : make_ulonglong2(0ull, 0ull);
        }

        // Side-load predicates: window cols x4-5 .. x4+8
        const bool eSL = (x4 >= 8);           // col  x4-5         (LDG.32)
        const bool eL1 = (x4 >= 4);           // cols x4-4..x4-1   (LDG.128)
        const bool eR1 = (tx <= 62);          // cols x4+4..x4+7   (LDG.128)
        const bool eSR = (tx <= 61);          // col  x4+8         (LDG.32)
        const float4 z4 = make_float4(0.f, 0.f, 0.f, 0.f);

        // Stage one 4-row group (rows Y+10..Y+13) and retire the group issued
        // one window earlier. Runs once per 4 iterations.
        #define CAX_STAGE(YY)                                                             \
        {                                                                                 \
            const int Ys = (YY);                                                          \
            _Pragma("unroll")                                                             \
            for (int t = 0; t < 4; t++) {                                                 \
                int row = Ys + 10 + t;                                                    \
                if (row < HH && row <= yEnd)                                              \
                    cpasync16((unsigned)__cvta_generic_to_shared(                         \
                                  &smem_ring[ty][row & 15][tx]),                          \
                              xc + (size_t)row * WW + x4);                                \
            }                                                                             \
            CP_COMMIT();                                                                  \
            CP_WAIT1();   /* group from window YY-4 done -> rows through YY+9 */          \
        }

        // Body for row y with register-ring phase u (compile-time constant).
        #define CAX_BODY(yy, uu)                                                          \
        {                                                                                 \
            const int y = (yy);                                                           \
            /* Register-ring fill: row y+6 from SMEM (LDS.128) */                         \
            {                                                                             \
                int row = y + 6;                                                          \
                ulonglong2 v = make_ulonglong2(0ull, 0ull);                               \
                if (row < HH) v = smem_ring[ty][row & 15][tx];                            \
                ring[((uu) + 11) % 12] = v;                                               \
            }                                                                             \
            /* Side loads for row y (L1 hits; lines brought by cp.async.ca) */            \
            const float* rowp = xc + (size_t)y * WW;                                      \
            float  sl = eSL ? rowp[x4 - 5] : 0.f;                                         \
            float4 l1 = eL1 ? *reinterpret_cast<const float4*>(rowp + x4 - 4) : z4;       \
            float4 r1 = eR1 ? *reinterpret_cast<const float4*>(rowp + x4 + 4) : z4;       \
            float  sr = eSR ? rowp[x4 + 8] : 0.f;                                         \
                                                                                          \
            ulonglong2 ctr = ring[((uu) + 5) % 12];     /* row y */                       \
            float c0, c1, c2, c3;                                                         \
            upk2(ctr.x, c0, c1);                                                          \
            upk2(ctr.y, c2, c3);                                                          \
                                                                                          \
            unsigned long long acc01 = ctr.x;                                             \
            unsigned long long acc23 = ctr.y;                                             \
            _Pragma("unroll")                                                             \
            for (int k = 0; k < 11; k++) {              /* row y + (k-5) */               \
                ulonglong2 rv2 = ring[((uu) + k) % 12];                                   \
                fma2(acc01, cwh2[k], rv2.x);                                              \
                fma2(acc23, cwh2[k], rv2.y);                                              \
            }                                                                             \
            float a0, a1, a2, a3;                                                         \
            upk2(acc01, a0, a1);                                                          \
            upk2(acc23, a2, a3);                                                          \
                                                                                          \
            float win[14];                                                                \
            win[0]  = sl;                                                                 \
            win[1]  = l1.x; win[2]  = l1.y; win[3]  = l1.z; win[4]  = l1.w;               \
            win[5]  = c0;   win[6]  = c1;   win[7]  = c2;   win[8]  = c3;                 \
            win[9]  = r1.x; win[10] = r1.y; win[11] = r1.z; win[12] = r1.w;               \
            win[13] = sr;                                                                 \
            _Pragma("unroll")                                                             \
            for (int k = 0; k < 11; k++) {              /* col (x4+j)+(k-5) */            \
                float w = cww[k];                                                         \
                a0 += w * win[k];                                                         \
                a1 += w * win[k + 1];                                                     \
                a2 += w * win[k + 2];                                                     \
                a3 += w * win[k + 3];                                                     \
            }                                                                             \
            __stcs(reinterpret_cast<float4*>(oc + (size_t)y * WW + x4),                   \
                   make_float4(a0, a1, a2, a3));                                          \
        }

        #pragma unroll 1
        for (int g = 0; g < 5; g++) {                 // 5 groups of 12 rows
            int ybase = y0 + g * 12;
            #pragma unroll
            for (int u = 0; u < 12; u++) {
                if (u == 0 || u == 4 || u == 8) CAX_STAGE(ybase + u)
                CAX_BODY(ybase + u, u)
            }
        }
        {                                             // tail: 4 rows (60..63)
            int ybase = y0 + 60;                      // 60 % 12 == 0 -> same phases
            #pragma unroll
            for (int u = 0; u < 4; u++) {
                if (u == 0) CAX_STAGE(ybase)          // empty group; retires prior
                CAX_BODY(ybase + u, u)
            }
        }
        #undef CAX_BODY
        #undef CAX_STAGE
    } else {
        // Generic path: direct 7-tap bilinear gather along both axes.
        #pragma unroll 1
        for (int yy = 0; yy < 64; yy++) {
            int y = y0 + yy;
            float acc[4];
            #pragma unroll
            for (int j = 0; j < 4; j++) acc[j] = xc[(size_t)y * WW + x4 + j];
            #pragma unroll
            for (int i = 0; i < KK; i++) {
                int   d  = k0i[i] - 5;
                float fr = fri[i];
                int r0 = y + d, r1 = r0 + 1;
                #pragma unroll
                for (int j = 0; j < 4; j++) {
                    int col = x4 + j;
                    float s0 = (r0 >= 0 && r0 < HH) ? xc[(size_t)r0 * WW + col] : 0.f;
                    float s1 = (r1 >= 0 && r1 < HH) ? xc[(size_t)r1 * WW + col] : 0.f;
                    acc[j] += whv[i] * (s0 * (1.f - fr) + s1 * fr);
                    int c0i = col + d, c1i = c0i + 1;
                    float t0 = (c0i >= 0 && c0i < WW) ? xc[(size_t)y * WW + c0i] : 0.f;
                    float t1 = (c1i >= 0 && c1i < WW) ? xc[(size_t)y * WW + c1i] : 0.f;
                    acc[j] += wwv[i] * (t0 * (1.f - fr) + t1 * fr);
                }
            }
            #pragma unroll
            for (int j = 0; j < 4; j++) oc[(size_t)y * WW + x4 + j] = acc[j];
        }
    }
}

extern "C" void kernel_launch(void* const* d_in, const int* in_sizes, int n_in,
                              void* d_out, int out_size) {
    const float* x  = (const float*)d_in[0];
    const float* wh = (const float*)d_in[1];
    const float* ww = (const float*)d_in[2];
    const float* r  = (const float*)d_in[3];
    float* out = (float*)d_out;

    int nimg = in_sizes[0] / (HH * WW);   // B*C = 768

    dim3 blk(64, 2, 1);
    dim3 grd(1, 2, nimg);
    caxial_kernel<<<grd, blk>>>(x, wh, ww, r, out);
}